// round 4
// baseline (speedup 1.0000x reference)
#include <cuda_runtime.h>
#include <cuda_bf16.h>

// ============================================================================
// Symmetric-contraction (MACE-style) kernel.
//
// res[n,c] = sum_x c0[c,x] f_x + sum_{x,i} c1[c,x,i] f_x f_i
//          + sum_{x,i,j} T[c,x,i,j] f_x f_i f_j,   f = node_feats[n,c,:]
//
// Fully symmetrized into 816 cubic + 136 quadratic + 16 linear monomials per
// channel. Main kernel: 2 atoms/thread via fma.rn.f32x2 packed fp32, coef
// stream broadcast from shared memory (duplicated u64, LDS.128 pairs).
// ============================================================================

#define NPOS 968            // 136 quad + 816 cubic (interleaved) + 16 linear
#define CCH  64
#define NI   16

__device__ float              g_Ustream[NPOS * 120];     // symmetrized U rows
__device__ unsigned long long g_Coef[CCH * NPOS];        // per-channel stream (dup'd)

// Decode stream position -> entry type + indices.
// Stream order (matches main-kernel consumption exactly):
//   for a in 0..15: for b in a..15: [QUAD(a,b)] then for e in b..15: [CUBIC(a,b,e)]
//   then 16 x [LIN(x)]
__device__ __forceinline__ void decode_pos(int pos, int& ty, int& a, int& b, int& e) {
    int pp = pos;
    for (int aa = 0; aa < 16; ++aa) {
        for (int bb = aa; bb < 16; ++bb) {
            if (pp == 0) { ty = 1; a = aa; b = bb; e = 0; return; }
            pp--;
            int cnt = 16 - bb;
            if (pp < cnt) { ty = 2; a = aa; b = bb; e = bb + pp; return; }
            pp -= cnt;
        }
    }
    ty = 0; a = pp; b = 0; e = 0;   // linear, a = x
}

// ---------------------------------------------------------------------------
// P1: symmetrize U tensors into the stream layout. grid = NPOS blocks, 128 thr.
// ---------------------------------------------------------------------------
__global__ void prep_u_kernel(const float* __restrict__ U2,
                              const float* __restrict__ U1,
                              const float* __restrict__ U0) {
    int pos = blockIdx.x;
    int k   = threadIdx.x;
    int ty, a, b, e;
    decode_pos(pos, ty, a, b, e);
    float s = 0.f;
    if (ty == 2) {                       // cubic: sum over distinct perms of (a,b,e)
        if (k >= 120) return;
#define U2AT(x, y, i) U2[((((x) * 16 + (y)) * 16 + (i)) * 120) + k]
        if (a == b && b == e)      s = U2AT(a, a, a);
        else if (a == b)           s = U2AT(a, a, e) + U2AT(a, e, a) + U2AT(e, a, a);
        else if (b == e)           s = U2AT(a, b, b) + U2AT(b, a, b) + U2AT(b, b, a);
        else                       s = U2AT(a, b, e) + U2AT(a, e, b) + U2AT(b, a, e)
                                     + U2AT(b, e, a) + U2AT(e, a, b) + U2AT(e, b, a);
#undef U2AT
    } else if (ty == 1) {                // quadratic: c1[a,b] + c1[b,a]
        if (k >= 8) return;
        s = (a == b) ? U1[(a * 16 + a) * 8 + k]
                     : U1[(a * 16 + b) * 8 + k] + U1[(b * 16 + a) * 8 + k];
    } else {                             // linear
        if (k >= 4) return;
        s = U0[a * 4 + k];
    }
    g_Ustream[pos * 120 + k] = s;
}

// ---------------------------------------------------------------------------
// P2: per-channel coefficient stream = Ustream . w. One thread per (pos, c).
// Values duplicated into both fp32 halves of a u64 for packed FMA.
// ---------------------------------------------------------------------------
__global__ void prep_coef_kernel(const float* __restrict__ w2,
                                 const float* __restrict__ w1,
                                 const float* __restrict__ w0) {
    int idx = blockIdx.x * blockDim.x + threadIdx.x;
    if (idx >= NPOS * CCH) return;
    int pos = idx >> 6;
    int c   = idx & 63;
    int ty, a, b, e;
    decode_pos(pos, ty, a, b, e);
    const float* us = g_Ustream + pos * 120;
    float v = 0.f;
    if (ty == 2) {
#pragma unroll
        for (int k = 0; k < 120; ++k) v += us[k] * w2[k * 64 + c];
    } else if (ty == 1) {
#pragma unroll
        for (int k = 0; k < 8; ++k)   v += us[k] * w1[k * 64 + c];
    } else {
#pragma unroll
        for (int k = 0; k < 4; ++k)   v += us[k] * w0[k * 64 + c];
    }
    unsigned u = __float_as_uint(v);
    g_Coef[c * NPOS + pos] = ((unsigned long long)u << 32) | (unsigned long long)u;
}

// ---------------------------------------------------------------------------
// Main kernel: each thread evaluates the cubic form for 2 atoms (packed f32x2)
// at one channel. Block = 256 threads -> 512 atoms per (block, channel).
// ---------------------------------------------------------------------------
#define MUL2(d, a, b)    asm("mul.rn.f32x2 %0, %1, %2;"     : "=l"(d) : "l"(a), "l"(b))
#define FMA2(d, a, b, c) asm("fma.rn.f32x2 %0, %1, %2, %3;" : "=l"(d) : "l"(a), "l"(b), "l"(c))
#define ADD2(d, a, b)    asm("add.rn.f32x2 %0, %1, %2;"     : "=l"(d) : "l"(a), "l"(b))

__global__ __launch_bounds__(256)
void sym_contract_kernel(const float* __restrict__ nf,
                         float* __restrict__ out,
                         int Natoms) {
    __shared__ __align__(16) unsigned long long scoef[NPOS];
    const int c = blockIdx.y;

    for (int i = threadIdx.x; i < NPOS; i += 256)
        scoef[i] = g_Coef[c * NPOS + i];
    __syncthreads();

    const int n0 = blockIdx.x * 512 + threadIdx.x;
    const int n1 = n0 + 256;

    float lo[NI], hi[NI];
#pragma unroll
    for (int i = 0; i < NI; ++i) { lo[i] = 0.f; hi[i] = 0.f; }

    if (n0 < Natoms) {
        const float4* p4 = reinterpret_cast<const float4*>(nf + ((size_t)n0 * 64 + c) * 16);
#pragma unroll
        for (int j = 0; j < 4; ++j) {
            float4 v = p4[j];
            lo[4 * j + 0] = v.x; lo[4 * j + 1] = v.y; lo[4 * j + 2] = v.z; lo[4 * j + 3] = v.w;
        }
    }
    if (n1 < Natoms) {
        const float4* p4 = reinterpret_cast<const float4*>(nf + ((size_t)n1 * 64 + c) * 16);
#pragma unroll
        for (int j = 0; j < 4; ++j) {
            float4 v = p4[j];
            hi[4 * j + 0] = v.x; hi[4 * j + 1] = v.y; hi[4 * j + 2] = v.z; hi[4 * j + 3] = v.w;
        }
    }

    unsigned long long F[NI];
#pragma unroll
    for (int i = 0; i < NI; ++i) {
        asm("mov.b64 %0, {%1, %2};" : "=l"(F[i])
            : "r"(__float_as_uint(lo[i])), "r"(__float_as_uint(hi[i])));
    }

    const ulonglong2* sc2 = reinterpret_cast<const ulonglong2*>(scoef);
    unsigned long long cb0 = 0, cb1 = 0;
    unsigned long long acc0 = 0ull, acc1 = 0ull, acc2 = 0ull, acc3 = 0ull;
    int p = 0;

#pragma unroll
    for (int a = 0; a < 16; ++a) {
#pragma unroll
        for (int b = a; b < 16; ++b) {
            unsigned long long gab;
            MUL2(gab, F[a], F[b]);
            // quadratic coefficient
            if ((p & 1) == 0) { ulonglong2 t = sc2[p >> 1]; cb0 = t.x; cb1 = t.y; }
            {
                unsigned long long cq = (p & 1) ? cb1 : cb0; p++;
                FMA2(acc0, cq, gab, acc0);
            }
#pragma unroll
            for (int e = b; e < 16; ++e) {
                unsigned long long m;
                MUL2(m, gab, F[e]);
                if ((p & 1) == 0) { ulonglong2 t = sc2[p >> 1]; cb0 = t.x; cb1 = t.y; }
                unsigned long long cc = (p & 1) ? cb1 : cb0; p++;
                int r = (a + b + e) % 3;
                if (r == 0)      FMA2(acc1, cc, m, acc1);
                else if (r == 1) FMA2(acc2, cc, m, acc2);
                else             FMA2(acc3, cc, m, acc3);
            }
        }
    }
    // linear terms
#pragma unroll
    for (int x = 0; x < 16; ++x) {
        if ((p & 1) == 0) { ulonglong2 t = sc2[p >> 1]; cb0 = t.x; cb1 = t.y; }
        unsigned long long cl = (p & 1) ? cb1 : cb0; p++;
        FMA2(acc0, cl, F[x], acc0);
    }

    ADD2(acc0, acc0, acc1);
    ADD2(acc2, acc2, acc3);
    ADD2(acc0, acc0, acc2);

    unsigned rl, rh;
    asm("mov.b64 {%0, %1}, %2;" : "=r"(rl), "=r"(rh) : "l"(acc0));
    if (n0 < Natoms) out[n0 * 64 + c] = __uint_as_float(rl);
    if (n1 < Natoms) out[n1 * 64 + c] = __uint_as_float(rh);
}

// ---------------------------------------------------------------------------
// Launch. Inputs (metadata order): node_feats, U2, U1, U0, w2, w1, w0.
// ---------------------------------------------------------------------------
extern "C" void kernel_launch(void* const* d_in, const int* in_sizes, int n_in,
                              void* d_out, int out_size) {
    const float* nf = (const float*)d_in[0];
    const float* U2 = (const float*)d_in[1];
    const float* U1 = (const float*)d_in[2];
    const float* U0 = (const float*)d_in[3];
    const float* w2 = (const float*)d_in[4];
    const float* w1 = (const float*)d_in[5];
    const float* w0 = (const float*)d_in[6];
    float* out = (float*)d_out;

    int Natoms = in_sizes[0] / (64 * 16);

    prep_u_kernel<<<NPOS, 128>>>(U2, U1, U0);
    prep_coef_kernel<<<(NPOS * CCH + 255) / 256, 256>>>(w2, w1, w0);

    dim3 grid((Natoms + 511) / 512, CCH);
    sym_contract_kernel<<<grid, 256>>>(nf, out, Natoms);
}